// round 10
// baseline (speedup 1.0000x reference)
#include <cuda_runtime.h>
#include <cstdint>

constexpr int B_ = 32;
constexpr int Q_ = 16384;
constexpr int G_ = 128;
constexpr int N_ = 9;
constexpr int HALF_Q = Q_ / 2;         // 8192 per warp
constexpr int GROUPS = HALF_Q / 128;   // 64 groups of 4x32 candidates

#define FULLM 0xFFFFFFFFu
#define PADF  3e-5f

// Sentinel key: hi = +inf bits; greater than any real key.
#define SENT (((uint64_t)0x7F800000u << 32) | 0xFFFFFFFFull)

// Precomputed |p|^2, lane-permuted so one LDG.128 per lane feeds the 4 chunks
// of a 128-candidate group: np_perm[b][t*128 + lane*4 + j] = |pred[b][t*128+j*32+lane]|^2
__device__ float np_perm[B_][Q_];

__global__ void precompute_np(const float4* __restrict__ pred) {
    const int idx = blockIdx.x * blockDim.x + threadIdx.x;
    if (idx >= B_ * Q_) return;
    const int b = idx >> 14;           // / Q_
    const int i = idx & (Q_ - 1);
    const float4 p = pred[(size_t)b * Q_ + i];
    const float np = fmaf(p.w, p.w, fmaf(p.z, p.z, fmaf(p.y, p.y, p.x * p.x)));
    const int t = i >> 7, r = i & 127, j = r >> 5, l = r & 31;
    np_perm[b][t * 128 + l * 4 + j] = np;
}

__global__ void __launch_bounds__(128)
atss_kernel(const float4* __restrict__ pred,
            const float4* __restrict__ gt,
            float* __restrict__ out,
            int out_elems) {
    const int wic  = threadIdx.x >> 5;   // warp in CTA: 0..3
    const int lane = threadIdx.x & 31;
    const int pair = wic >> 1;           // GT slot within CTA: 0..1
    const int half = wic & 1;            // which half of Q this warp scans
    const int gt_lin = blockIdx.x * 2 + pair;        // 0..4095
    const int b = gt_lin >> 7;
    const int g = gt_lin & (G_ - 1);

    const float4* __restrict__ pb = pred + (size_t)b * Q_;
    const float4 gv = gt[gt_lin];
    const float g2 = fmaf(gv.w, gv.w, fmaf(gv.z, gv.z,
                       fmaf(gv.y, gv.y, gv.x * gv.x)));   // screening only

    // Shared padded screening bounds (u-space), one per (pair, half).
    __shared__ volatile float su[2][2];
    __shared__ uint64_t sp[2][32];
    if (lane == 0) su[pair][half] = __uint_as_float(0x7F800000u);
    __syncthreads();
    volatile float* uo = &su[pair][1 - half];   // other warp's bound

    // ---- Stage 1: this warp's share of global top-32 smallest (d2, idx). ----
    uint64_t pool   = SENT;              // sorted ascending across lanes
    uint64_t curmax = SENT;              // == pool[31]
    float    u      = __uint_as_float(0x7F800000u);  // own padded bound

    const float4* __restrict__ npv =
        (const float4*)np_perm[b] + (half * GROUPS) * 32 + lane;
    const float4* __restrict__ ph = pb + half * HALF_Q;

    for (int t = 0; t < GROUPS; t++) {
        const float4* gp = ph + t * 128 + lane;
        const float4 p0 = __ldg(gp);
        const float4 p1 = __ldg(gp + 32);
        const float4 p2 = __ldg(gp + 64);
        const float4 p3 = __ldg(gp + 96);
        const float4 np4 = __ldg(npv + t * 32);

        // Screening value v = |p|^2 - 2*(g.p); v <= t2 - g2 + PAD  <=>  pass.
        float v[4];
        #define DOTV(dst, P, NP) { \
            float dt_ = fmaf(P.w, gv.w, fmaf(P.z, gv.z, \
                        fmaf(P.y, gv.y, P.x * gv.x))); \
            dst = fmaf(dt_, -2.0f, NP); }
        DOTV(v[0], p0, np4.x) DOTV(v[1], p1, np4.y)
        DOTV(v[2], p2, np4.z) DOTV(v[3], p3, np4.w)
        #undef DOTV

        float us = fminf(u, *uo);        // shared (tighter) bound
        const float vmin = fminf(fminf(v[0], v[1]), fminf(v[2], v[3]));
        if (__any_sync(FULLM, vmin <= us)) {
            const int base = (half * GROUPS + t) * 128;
            #pragma unroll
            for (int j = 0; j < 4; j++) {
                unsigned m = __ballot_sync(FULLM, v[j] <= us);
                while (m) {
                    const int src = __ffs(m) - 1;
                    m &= m - 1;
                    const int ci = base + j * 32 + src;
                    // Exact XLA rn-chain d2 (broadcast reload, L1-hot, rare).
                    const float4 cp = __ldg(pb + ci);
                    const float dx = __fsub_rn(gv.x, cp.x);
                    const float dy = __fsub_rn(gv.y, cp.y);
                    const float dw = __fsub_rn(gv.z, cp.z);
                    const float dh = __fsub_rn(gv.w, cp.w);
                    const float d2e = __fadd_rn(__fadd_rn(__fadd_rn(
                                          __fmul_rn(dx, dx), __fmul_rn(dy, dy)),
                                          __fmul_rn(dw, dw)), __fmul_rn(dh, dh));
                    const uint64_t cand =
                        ((uint64_t)__float_as_uint(d2e) << 32) | (unsigned)ci;
                    if (cand < curmax) {            // warp-uniform exact test
                        const unsigned gtm = __ballot_sync(FULLM, pool > cand);
                        const uint64_t prev = __shfl_up_sync(FULLM, pool, 1);
                        const int ppos = __ffs(gtm) - 1;
                        if (pool > cand) pool = (lane == ppos) ? cand : prev;
                        curmax = __shfl_sync(FULLM, pool, 31);
                        const float t2f =
                            __uint_as_float((unsigned)(curmax >> 32));
                        u = __fadd_rn(__fsub_rn(t2f, g2), PADF);
                        if (lane == 0) su[pair][half] = u;
                        us = fminf(u, *uo);
                    }
                }
            }
        }
    }

    // ---- Merge the two half-pools (exact): lower half of bitonic merge. ----
    if (half == 1) sp[pair][lane] = pool;
    __syncthreads();
    if (half == 1) return;

    {
        const uint64_t bk = sp[pair][31 - lane];
        uint64_t v2 = (pool < bk) ? pool : bk;
        #pragma unroll
        for (int j = 16; j; j >>= 1) {
            const uint64_t o = __shfl_xor_sync(FULLM, v2, j);
            const uint64_t mnv = (v2 < o) ? v2 : o;
            const uint64_t mxv = (v2 < o) ? o : v2;
            v2 = ((lane & j) == 0) ? mnv : mxv;
        }
        pool = v2;
    }

    // ---- Re-rank by (sqrt(d2) bits, idx) == JAX's (d, idx); full sort. ------
    unsigned pidx = (unsigned)(pool & 0xFFFFFFFFull);
    {
        const float dval = __fsqrt_rn(__uint_as_float((unsigned)(pool >> 32)));
        uint64_t skey = ((uint64_t)__float_as_uint(dval) << 32) | pidx;
        #pragma unroll
        for (int k = 2; k <= 32; k <<= 1) {
            #pragma unroll
            for (int j = k >> 1; j; j >>= 1) {
                const uint64_t o = __shfl_xor_sync(FULLM, skey, j);
                const bool lower = (lane & j) == 0;
                const bool asc   = (lane & k) == 0;
                const uint64_t mnv = (skey < o) ? skey : o;
                const uint64_t mxv = (skey < o) ? o : skey;
                skey = (lower == asc) ? mnv : mxv;
            }
        }
        pidx = (unsigned)(skey & 0xFFFFFFFFull);
    }
    const int rank = lane;

    // ---- Stage 2: IoU(gt, candidate), explicit rn ops (no contraction). -----
    const float4 p = __ldg(pb + pidx);
    const float gx0 = __fsub_rn(gv.x, __fmul_rn(0.5f, gv.z));
    const float gx1 = __fadd_rn(gv.x, __fmul_rn(0.5f, gv.z));
    const float gy0 = __fsub_rn(gv.y, __fmul_rn(0.5f, gv.w));
    const float gy1 = __fadd_rn(gv.y, __fmul_rn(0.5f, gv.w));
    const float px0 = __fsub_rn(p.x,  __fmul_rn(0.5f, p.z));
    const float px1 = __fadd_rn(p.x,  __fmul_rn(0.5f, p.z));
    const float py0 = __fsub_rn(p.y,  __fmul_rn(0.5f, p.w));
    const float py1 = __fadd_rn(p.y,  __fmul_rn(0.5f, p.w));

    const float ltx = fmaxf(gx0, px0), lty = fmaxf(gy0, py0);
    const float rbx = fminf(gx1, px1), rby = fminf(gy1, py1);
    const float iw = fmaxf(__fsub_rn(rbx, ltx), 0.0f);
    const float ih = fmaxf(__fsub_rn(rby, lty), 0.0f);
    const float inter = __fmul_rn(iw, ih);
    const float areaA = __fmul_rn(__fsub_rn(gx1, gx0), __fsub_rn(gy1, gy0));
    const float areaB = __fmul_rn(__fsub_rn(px1, px0), __fsub_rn(py1, py0));
    const float uni   = __fsub_rn(__fadd_rn(areaA, areaB), inter);
    const float iou   = __fdiv_rn(inter, uni);

    // ---- top-9 by IoU, ties -> smaller rank: descending bitonic sort. -------
    uint64_t ikey = ((uint64_t)__float_as_uint(iou) << 32)
                  | (unsigned)(32 - rank);
    #pragma unroll
    for (int k = 2; k <= 32; k <<= 1) {
        #pragma unroll
        for (int j = k >> 1; j; j >>= 1) {
            const uint64_t o = __shfl_xor_sync(FULLM, ikey, j);
            const bool lower = (lane & j) == 0;
            const bool desc  = (lane & k) == 0;
            const uint64_t mnv = (ikey < o) ? ikey : o;
            const uint64_t mxv = (ikey < o) ? o : ikey;
            ikey = (lower == desc) ? mxv : mnv;
        }
    }
    const int rsel = 32 - (int)(ikey & 63);
    const unsigned psel = __shfl_sync(FULLM, pidx, rsel);

    const int obase = gt_lin * N_;
    if (lane < N_ && obase + lane < out_elems)
        out[obase + lane] = (float)psel;
    const int gbase = B_ * G_ * N_ + obase;
    if (lane < N_ && gbase + lane < out_elems)
        out[gbase + lane] = (float)g;
}

extern "C" void kernel_launch(void* const* d_in, const int* in_sizes, int n_in,
                              void* d_out, int out_size) {
    const float4* pred = (const float4*)d_in[0];
    const float4* gt   = (const float4*)d_in[1];
    if (n_in >= 2 && in_sizes[0] < in_sizes[1]) {   // robust input ordering
        pred = (const float4*)d_in[1];
        gt   = (const float4*)d_in[0];
    }
    precompute_np<<<(B_ * Q_ + 255) / 256, 256>>>(pred);
    atss_kernel<<<(B_ * G_) / 2, 128>>>(pred, gt, (float*)d_out, out_size);
}